// round 10
// baseline (speedup 1.0000x reference)
#include <cuda_runtime.h>
#include <math.h>

#define XS   256
#define BB   16
#define HALFK 129               // XS/2 + 1
#define NPIX (BB * XS * XS)
// region layout for one 256-pt transform: element n at 17*(n>>4) + (n&15)
#define LX(n) ((((n) >> 4) * 17) + ((n) & 15))
#define REG_STRIDE 274          // float2 units per transform region (272 + pad)

// ---------------- scratch (device globals: no allocation allowed) ----------
__device__ float  g_prep[BB * 16];      // per batch: R00..R12 (6), s0, s1, h[8]
__device__ float  g_gauss[7];
__device__ float  g_img[NPIX];          // scatter target
__device__ float2 g_A[BB * XS * HALFK]; // half-spectrum [b][y/ky][kx]

// ---------------- fused zero + prep + gaussian taps ----------------
__global__ void zero_prep_kernel(const float* __restrict__ rows,
                                 const float* __restrict__ shifts,
                                 const float* __restrict__ latent,
                                 const float* __restrict__ W0, const float* __restrict__ b0,
                                 const float* __restrict__ W1, const float* __restrict__ b1,
                                 const float* __restrict__ W2, const float* __restrict__ b2,
                                 const float* __restrict__ W3, const float* __restrict__ b3) {
    if (blockIdx.x == 0) {
        int b = threadIdx.x;
        if (b < BB) {
            float rot = rows[b*3+0], tilt = rows[b*3+1], psi = rows[b*3+2];
            float ca = cosf(rot),  sa = sinf(rot);
            float cb = cosf(tilt), sb = sinf(tilt);
            float cg = cosf(psi),  sg = sinf(psi);
            float nsg = -sg;
            float* p = &g_prep[b * 16];
            p[0] = __fsub_rn(__fmul_rn(__fmul_rn(cg, cb), ca), __fmul_rn(sg, sa));
            p[1] = __fadd_rn(__fmul_rn(__fmul_rn(cg, cb), sa), __fmul_rn(sg, ca));
            p[2] = -__fmul_rn(cg, sb);
            p[3] = __fsub_rn(__fmul_rn(__fmul_rn(nsg, cb), ca), __fmul_rn(cg, sa));
            p[4] = __fadd_rn(__fmul_rn(__fmul_rn(nsg, cb), sa), __fmul_rn(cg, ca));
            p[5] = __fmul_rn(sg, sb);
            p[6] = shifts[b*2+0];
            p[7] = shifts[b*2+1];

            float h[8];
            #pragma unroll
            for (int j = 0; j < 8; j++) {
                float acc = b0[j];
                #pragma unroll
                for (int l = 0; l < 8; l++) acc += latent[b*8+l] * W0[l*8+j];
                h[j] = sinf(30.0f * acc);
            }
            const float* Ws[3] = {W1, W2, W3};
            const float* bs[3] = {b1, b2, b3};
            for (int s = 0; s < 3; s++) {
                float t[8];
                #pragma unroll
                for (int j = 0; j < 8; j++) {
                    float acc = bs[s][j];
                    #pragma unroll
                    for (int l = 0; l < 8; l++) acc += h[l] * Ws[s][l*8+j];
                    t[j] = sinf(acc);
                }
                #pragma unroll
                for (int j = 0; j < 8; j++) h[j] += t[j];
            }
            #pragma unroll
            for (int j = 0; j < 8; j++) p[8+j] = h[j];
        }
        if (threadIdx.x == 0) {
            float k[7], s = 0.f;
            for (int i = 0; i < 7; i++) { float x = (float)(i - 3); k[i] = expf(-0.5f * x * x); s += k[i]; }
            for (int i = 0; i < 7; i++) g_gauss[i] = k[i] / s;
        }
    }
    int i = blockIdx.x * blockDim.x + threadIdx.x;
    float4* p4 = (float4*)g_img;
    if (i < NPIX / 4) p4[i] = make_float4(0.f, 0.f, 0.f, 0.f);
}

// ---------------- scatter (arithmetic bit-identical to passing rounds) ------
__global__ void scatter_kernel(const float* __restrict__ coords,
                               const float* __restrict__ values,
                               const float* __restrict__ Wd,
                               const float* __restrict__ bd,
                               int N) {
    __shared__ float sp[256];  // 16 batches x 16 floats
    if (threadIdx.x < 256) sp[threadIdx.x] = g_prep[threadIdx.x];
    __syncthreads();

    int n = blockIdx.x * blockDim.x + threadIdx.x;
    if (n >= N) return;

    float cx = coords[n*3+0], cy = coords[n*3+1], cz = coords[n*3+2];
    float base = values[n] + bd[n];
    float wd[8];
    #pragma unroll
    for (int l = 0; l < 8; l++) wd[l] = Wd[(size_t)l * N + n];

    #pragma unroll
    for (int b = 0; b < BB; b++) {
        const float* p = &sp[b * 16];
        float xr = __fmaf_rn(p[2], cz, __fmaf_rn(p[1], cy, __fmul_rn(p[0], cx)));
        float yr = __fmaf_rn(p[5], cz, __fmaf_rn(p[4], cy, __fmul_rn(p[3], cx)));
        float fx = rintf(__fadd_rn(__fadd_rn(xr, p[6]), 128.0f));
        float fy = rintf(__fadd_rn(__fadd_rn(yr, p[7]), 128.0f));
        fx = fminf(fmaxf(fx, 0.f), 255.f);
        fy = fminf(fmaxf(fy, 0.f), 255.f);
        int ix = (int)fx, iy = (int)fy;
        float val = base;
        #pragma unroll
        for (int l = 0; l < 8; l++) val = fmaf(p[8+l], wd[l], val);
        atomicAdd(&g_img[(b << 16) + (iy << 8) + ix], val);
    }
}

// ---------------- 256-pt FFT = 16 (regs) x 16 (regs) + one smem transpose --
// Transform owned by 16 threads (u = lane 0..15). SGN=-1 fwd, +1 inv.
__device__ __forceinline__ void bfly(float2& a, float2& b, float wx, float wy) {
    float dx = a.x - b.x, dy = a.y - b.y;
    a.x += b.x; a.y += b.y;
    b.x = fmaf(wx, dx, -wy * dy);
    b.y = fmaf(wx, dy,  wy * dx);
}

// 16-pt radix-2 DIF in registers; output bit-reversed: v[r] = X[br4(r)].
template<int SGN>
__device__ __forceinline__ void fft16r(float2* v) {
    const float s  = (float)SGN;
    const float C1 = 0.92387953251128674f;   // cos(pi/8)
    const float S1 = 0.38268343236508978f;   // sin(pi/8)
    const float Hq = 0.70710678118654752f;   // sqrt(2)/2
    bfly(v[0], v[8],  1.f, 0.f);
    bfly(v[1], v[9],  C1,  s*S1);
    bfly(v[2], v[10], Hq,  s*Hq);
    bfly(v[3], v[11], S1,  s*C1);
    bfly(v[4], v[12], 0.f, s);
    bfly(v[5], v[13], -S1, s*C1);
    bfly(v[6], v[14], -Hq, s*Hq);
    bfly(v[7], v[15], -C1, s*S1);
    #pragma unroll
    for (int o = 0; o < 16; o += 8) {
        bfly(v[o+0], v[o+4], 1.f, 0.f);
        bfly(v[o+1], v[o+5], Hq,  s*Hq);
        bfly(v[o+2], v[o+6], 0.f, s);
        bfly(v[o+3], v[o+7], -Hq, s*Hq);
    }
    #pragma unroll
    for (int o = 0; o < 16; o += 4) {
        bfly(v[o+0], v[o+2], 1.f, 0.f);
        bfly(v[o+1], v[o+3], 0.f, s);
    }
    #pragma unroll
    for (int o = 0; o < 16; o += 2) bfly(v[o], v[o+1], 1.f, 0.f);
}

#define BR4_INIT const int br[16] = {0,8,4,12,2,10,6,14,1,9,5,13,3,11,7,15}

// Full 256-pt transform. In: v[n1] = x[16*n1 + u]. Out: v[r] = X[u + 16*br[r]].
// S = this transform's 274-float2 region (used as 16x17 transpose scratch).
// tw[j] = e^{+2pi i j/256}. Internal syncwarps also order any caller smem
// reads (into v) before S is overwritten.
template<int SGN>
__device__ __forceinline__ void fft256_16(float2* v, float2* S,
                                          const float2* tw, int u) {
    BR4_INIT;
    fft16r<SGN>(v);                       // v[r] = A[br[r]]
    __syncwarp();
    #pragma unroll
    for (int r = 0; r < 16; r++) {
        int q = br[r];
        float2 w = tw[u * q];
        float wy = (SGN < 0) ? -w.y : w.y;
        float2 a = v[r];
        S[q * 17 + u] = make_float2(fmaf(w.x, a.x, -wy * a.y),
                                    fmaf(w.x, a.y,  wy * a.x));
    }
    __syncwarp();
    #pragma unroll
    for (int n2 = 0; n2 < 16; n2++) v[n2] = S[u * 17 + n2];
    fft16r<SGN>(v);                       // v[r] = X[u + 16*br[r]]
}

__device__ __forceinline__ void fill_tw256(float2* tw, int tid) {
    for (int i = tid; i < 256; i += 128) {
        float s, c;
        sincospif((float)i / 128.0f, &s, &c);
        tw[i] = make_float2(c, s);
    }
}

// Stage A: x-blur + forward rfft of TWO rows packed per transform.
// 128-thread block = 8 transforms = 16 rows.
__global__ __launch_bounds__(128, 8) void fftA_kernel() {
    __shared__ float2 sm[8 * REG_STRIDE + 256];
    float2* tw = sm + 8 * REG_STRIDE;
    int tid = threadIdx.x;
    int c = tid >> 4, u = tid & 15;
    float2* S = sm + REG_STRIDE * c;
    int b  = blockIdx.x >> 4;
    int y0 = (blockIdx.x & 15) * 16;
    const float* src = &g_img[(b * 256 + y0) * 256];

    // stage 16 rows as packed pairs: region tr slot x = (row 2tr, row 2tr+1)
    for (int i = tid; i < 2048; i += 128) {
        int tr = i >> 8, x = i & 255;
        float va = src[(2 * tr)     * 256 + x];
        float vb = src[(2 * tr + 1) * 256 + x];
        sm[REG_STRIDE * tr + LX(x)] = make_float2(va, vb);
    }
    fill_tw256(tw, tid);
    float w[7];
    #pragma unroll
    for (int i = 0; i < 7; i++) w[i] = g_gauss[i];
    __syncthreads();

    // x-blur (zero-padded SAME) into registers
    float2 v[16];
    #pragma unroll
    for (int n1 = 0; n1 < 16; n1++) {
        int n = 16 * n1 + u;
        float ax = 0.f, ay = 0.f;
        #pragma unroll
        for (int d = -3; d <= 3; d++) {
            int nn = n + d;
            if (nn >= 0 && nn < 256) {
                float2 rv = S[LX(nn)];
                ax = fmaf(w[d+3], rv.x, ax);
                ay = fmaf(w[d+3], rv.y, ay);
            }
        }
        v[n1] = make_float2(ax, ay);
    }
    fft256_16<-1>(v, S, tw, u);

    // write natural order, then Hermitian unpack
    BR4_INIT;
    __syncwarp();
    #pragma unroll
    for (int r = 0; r < 16; r++) S[br[r] * 17 + u] = v[r];
    __syncwarp();

    float2* o1 = &g_A[(size_t)(b * 256 + y0 + 2 * c) * HALFK];
    float2* o2 = o1 + HALFK;
    #pragma unroll
    for (int j = 0; j < 8; j++) {
        int kx = u + 16 * j;                 // 0..127
        float2 Z1 = S[LX(kx)];
        float2 Z2 = S[LX((256 - kx) & 255)];
        o1[kx] = make_float2(0.5f*(Z1.x + Z2.x), 0.5f*(Z1.y - Z2.y));
        o2[kx] = make_float2(0.5f*(Z1.y + Z2.y), 0.5f*(Z2.x - Z1.x));
    }
    if (u == 0) {
        float2 Zn = S[LX(128)];
        o1[128] = make_float2(Zn.x, 0.f);
        o2[128] = make_float2(Zn.y, 0.f);
    }
}

// Stage B: y-blur + column fwd FFT + CTF + column inv FFT.
// 128-thread block = 8 kx columns.
__global__ __launch_bounds__(128, 8) void fftB_kernel(const float* __restrict__ ctf) {
    __shared__ float2 sm[8 * REG_STRIDE + 256];
    float2* tw = sm + 8 * REG_STRIDE;
    int tid = threadIdx.x;
    int c = tid >> 4, u = tid & 15;
    float2* S = sm + REG_STRIDE * c;
    int b   = blockIdx.x / 17;
    int kx0 = (blockIdx.x % 17) * 8;

    for (int i = tid; i < 2048; i += 128) {
        int kxo = i & 7, ky = i >> 3;
        sm[REG_STRIDE * kxo + LX(ky)] =
            g_A[(size_t)(b * 256 + ky) * HALFK + min(kx0 + kxo, 128)];
    }
    fill_tw256(tw, tid);
    float w[7];
    #pragma unroll
    for (int i = 0; i < 7; i++) w[i] = g_gauss[i];
    __syncthreads();

    // y-blur (zero-padded) into registers; index here is spatial y
    float2 v[16];
    #pragma unroll
    for (int n1 = 0; n1 < 16; n1++) {
        int n = 16 * n1 + u;
        float ax = 0.f, ay = 0.f;
        #pragma unroll
        for (int d = -3; d <= 3; d++) {
            int nn = n + d;
            if (nn >= 0 && nn < 256) {
                float2 rv = S[LX(nn)];
                ax = fmaf(w[d+3], rv.x, ax);
                ay = fmaf(w[d+3], rv.y, ay);
            }
        }
        v[n1] = make_float2(ax, ay);
    }
    fft256_16<-1>(v, S, tw, u);

    // CTF multiply in registers (spectral index k = u + 16*br[r])
    BR4_INIT;
    int kxc = min(kx0 + c, 128);
    #pragma unroll
    for (int r = 0; r < 16; r++) {
        int k = u + 16 * br[r];
        float f = ctf[(size_t)(b * 256 + k) * HALFK + kxc];
        v[r].x *= f; v[r].y *= f;
    }
    // natural-order store, reload transposed, inverse FFT
    __syncwarp();
    #pragma unroll
    for (int r = 0; r < 16; r++) S[br[r] * 17 + u] = v[r];
    __syncwarp();
    #pragma unroll
    for (int n1 = 0; n1 < 16; n1++) v[n1] = S[n1 * 17 + u];
    fft256_16<1>(v, S, tw, u);

    __syncwarp();
    #pragma unroll
    for (int r = 0; r < 16; r++) S[br[r] * 17 + u] = v[r];
    __syncthreads();

    for (int i = tid; i < 2048; i += 128) {
        int kxo = i & 7, ky = i >> 3;
        int kx = kx0 + kxo;
        if (kx <= 128)
            g_A[(size_t)(b * 256 + ky) * HALFK + kx] = sm[REG_STRIDE * kxo + LX(ky)];
    }
}

// Stage D: inverse rfft of TWO rows per transform (S1 + i*S2 pack).
// Im of DC/Nyquist dropped (irfft semantics; keeps pack exactly Hermitian).
// Hermitian pack built gmem -> registers directly; direct coalesced output.
__global__ __launch_bounds__(128, 8) void fftD_kernel(float* __restrict__ out) {
    __shared__ float2 sm[8 * REG_STRIDE + 256];
    float2* tw = sm + 8 * REG_STRIDE;
    int tid = threadIdx.x;
    int c = tid >> 4, u = tid & 15;
    float2* S = sm + REG_STRIDE * c;
    int b  = blockIdx.x >> 4;
    int y0 = (blockIdx.x & 15) * 16 + 2 * c;
    const float2* A1 = &g_A[(size_t)(b * 256 + y0) * HALFK];
    const float2* A2 = A1 + HALFK;

    fill_tw256(tw, tid);
    __syncthreads();

    float2 v[16];
    #pragma unroll
    for (int n1 = 0; n1 < 16; n1++) {
        int k = 16 * n1 + u;
        float2 z;
        if (k == 0)        z = make_float2(A1[0].x,   A2[0].x);
        else if (k == 128) z = make_float2(A1[128].x, A2[128].x);
        else if (k < 128) {
            float2 a1 = A1[k], a2 = A2[k];
            z = make_float2(a1.x - a2.y, a1.y + a2.x);
        } else {
            int m = 256 - k;
            float2 m1 = A1[m], m2 = A2[m];
            z = make_float2(m1.x + m2.y, m2.x - m1.y);
        }
        v[n1] = z;
    }
    fft256_16<1>(v, S, tw, u);

    const float sc = 1.0f / 65536.0f;    // 1/(256*256)
    float* o0 = &out[(size_t)(b * 256 + y0) * 256];
    float* o1 = o0 + 256;
    BR4_INIT;
    #pragma unroll
    for (int r = 0; r < 16; r++) {
        int x = u + 16 * br[r];
        o0[x] = v[r].x * sc;
        o1[x] = v[r].y * sc;
    }
}

// ---------------- launch ----------------
extern "C" void kernel_launch(void* const* d_in, const int* in_sizes, int n_in,
                              void* d_out, int out_size) {
    const float* rows   = (const float*)d_in[0];
    const float* shifts = (const float*)d_in[1];
    const float* latent = (const float*)d_in[2];
    const float* coords = (const float*)d_in[3];
    const float* values = (const float*)d_in[4];
    const float* W0 = (const float*)d_in[5];
    const float* b0 = (const float*)d_in[6];
    const float* W1 = (const float*)d_in[7];
    const float* b1 = (const float*)d_in[8];
    const float* W2 = (const float*)d_in[9];
    const float* b2 = (const float*)d_in[10];
    const float* W3 = (const float*)d_in[11];
    const float* b3 = (const float*)d_in[12];
    const float* Wd = (const float*)d_in[13];
    const float* bd = (const float*)d_in[14];
    const float* ctf = (const float*)d_in[15];
    int N = in_sizes[4];

    zero_prep_kernel<<<NPIX / 4 / 256, 256>>>(rows, shifts, latent,
                                              W0, b0, W1, b1, W2, b2, W3, b3);
    scatter_kernel<<<(N + 255) / 256, 256>>>(coords, values, Wd, bd, N);
    fftA_kernel<<<BB * 16, 128>>>();
    fftB_kernel<<<BB * 17, 128>>>(ctf);
    fftD_kernel<<<BB * 16, 128>>>((float*)d_out);
}

// round 14
// speedup vs baseline: 1.4273x; 1.4273x over previous
#include <cuda_runtime.h>
#include <math.h>

#define XS   256
#define BB   16
#define HALFK 129               // XS/2 + 1 (logical)
#define AST   132               // allocated g_A row stride: 132*8B = 1056B ≡ 0 mod 32
#define NPIX (BB * XS * XS)
#define SK(i) ((i) + ((i) >> 5))   // smem bank skew

// ---------------- scratch (device globals: no allocation allowed) ----------
__device__ float  g_prep[BB * 16];      // per batch: R00..R12 (6), s0, s1, h[8]
__device__ float  g_gauss[7];
__device__ float  g_img[NPIX];          // scatter target
__device__ __align__(128) float2 g_A[BB * XS * AST]; // half-spectrum [b][y/ky][kx]

// 64-thread named barrier (2 warps of one transform). ids 1..4.
__device__ __forceinline__ void barx(int id) {
    asm volatile("bar.sync %0, 64;" :: "r"(id) : "memory");
}

// ---------------- fused zero + prep + gaussian taps ----------------
__global__ void zero_prep_kernel(const float* __restrict__ rows,
                                 const float* __restrict__ shifts,
                                 const float* __restrict__ latent,
                                 const float* __restrict__ W0, const float* __restrict__ b0,
                                 const float* __restrict__ W1, const float* __restrict__ b1,
                                 const float* __restrict__ W2, const float* __restrict__ b2,
                                 const float* __restrict__ W3, const float* __restrict__ b3) {
    if (blockIdx.x == 0) {
        int b = threadIdx.x;
        if (b < BB) {
            float rot = rows[b*3+0], tilt = rows[b*3+1], psi = rows[b*3+2];
            float ca = cosf(rot),  sa = sinf(rot);
            float cb = cosf(tilt), sb = sinf(tilt);
            float cg = cosf(psi),  sg = sinf(psi);
            float nsg = -sg;
            float* p = &g_prep[b * 16];
            p[0] = __fsub_rn(__fmul_rn(__fmul_rn(cg, cb), ca), __fmul_rn(sg, sa));
            p[1] = __fadd_rn(__fmul_rn(__fmul_rn(cg, cb), sa), __fmul_rn(sg, ca));
            p[2] = -__fmul_rn(cg, sb);
            p[3] = __fsub_rn(__fmul_rn(__fmul_rn(nsg, cb), ca), __fmul_rn(cg, sa));
            p[4] = __fadd_rn(__fmul_rn(__fmul_rn(nsg, cb), sa), __fmul_rn(cg, ca));
            p[5] = __fmul_rn(sg, sb);
            p[6] = shifts[b*2+0];
            p[7] = shifts[b*2+1];

            float h[8];
            #pragma unroll
            for (int j = 0; j < 8; j++) {
                float acc = b0[j];
                #pragma unroll
                for (int l = 0; l < 8; l++) acc += latent[b*8+l] * W0[l*8+j];
                h[j] = sinf(30.0f * acc);
            }
            const float* Ws[3] = {W1, W2, W3};
            const float* bs[3] = {b1, b2, b3};
            for (int s = 0; s < 3; s++) {
                float t[8];
                #pragma unroll
                for (int j = 0; j < 8; j++) {
                    float acc = bs[s][j];
                    #pragma unroll
                    for (int l = 0; l < 8; l++) acc += h[l] * Ws[s][l*8+j];
                    t[j] = sinf(acc);
                }
                #pragma unroll
                for (int j = 0; j < 8; j++) h[j] += t[j];
            }
            #pragma unroll
            for (int j = 0; j < 8; j++) p[8+j] = h[j];
        }
        if (threadIdx.x == 0) {
            float k[7], s = 0.f;
            for (int i = 0; i < 7; i++) { float x = (float)(i - 3); k[i] = expf(-0.5f * x * x); s += k[i]; }
            for (int i = 0; i < 7; i++) g_gauss[i] = k[i] / s;
        }
    }
    int i = blockIdx.x * blockDim.x + threadIdx.x;
    float4* p4 = (float4*)g_img;
    if (i < NPIX / 4) p4[i] = make_float4(0.f, 0.f, 0.f, 0.f);
}

// ---------------- scatter (arithmetic bit-identical to passing rounds) ------
__global__ void scatter_kernel(const float* __restrict__ coords,
                               const float* __restrict__ values,
                               const float* __restrict__ Wd,
                               const float* __restrict__ bd,
                               int N) {
    __shared__ float sp[256];  // 16 batches x 16 floats
    if (threadIdx.x < 256) sp[threadIdx.x] = g_prep[threadIdx.x];
    __syncthreads();

    int n = blockIdx.x * blockDim.x + threadIdx.x;
    if (n >= N) return;

    float cx = coords[n*3+0], cy = coords[n*3+1], cz = coords[n*3+2];
    float base = values[n] + bd[n];
    float wd[8];
    #pragma unroll
    for (int l = 0; l < 8; l++) wd[l] = Wd[(size_t)l * N + n];

    #pragma unroll
    for (int b = 0; b < BB; b++) {
        const float* p = &sp[b * 16];
        float xr = __fmaf_rn(p[2], cz, __fmaf_rn(p[1], cy, __fmul_rn(p[0], cx)));
        float yr = __fmaf_rn(p[5], cz, __fmaf_rn(p[4], cy, __fmul_rn(p[3], cx)));
        float fx = rintf(__fadd_rn(__fadd_rn(xr, p[6]), 128.0f));
        float fy = rintf(__fadd_rn(__fadd_rn(yr, p[7]), 128.0f));
        fx = fminf(fmaxf(fx, 0.f), 255.f);
        fy = fminf(fmaxf(fy, 0.f), 255.f);
        int ix = (int)fx, iy = (int)fy;
        float val = base;
        #pragma unroll
        for (int l = 0; l < 8; l++) val = fmaf(p[8+l], wd[l], val);
        atomicAdd(&g_img[(b << 16) + (iy << 8) + ix], val);
    }
}

// ---------------- radix-4 Stockham 256-pt FFT (64 threads / transform) -----
// tw[k] = e^{+2pi i k/256}. sgn=-1 fwd, +1 inv (unnormalized). Result in b0.
// Per-stage sync uses a NAMED 64-thread barrier (slices private per transform).
__device__ __forceinline__ float2 cmul_sgn(float2 w, float2 v, float sgn) {
    float wy = sgn * w.y;
    return make_float2(fmaf(w.x, v.x, -wy * v.y), fmaf(w.x, v.y, wy * v.x));
}

__device__ __forceinline__ void fft256_r4(float2* b0, float2* b1, const float2* tw,
                                          int o, int t, float sgn, int bid) {
    float2 *a = b0, *b = b1;
    #pragma unroll
    for (int m = 1; m < 256; m <<= 2) {
        int k = t & ~(m - 1);
        float2 c0 = a[SK(o + t)],       c1 = a[SK(o + t + 64)];
        float2 c2 = a[SK(o + t + 128)], c3 = a[SK(o + t + 192)];
        float2 t0 = make_float2(c0.x + c2.x, c0.y + c2.y);
        float2 t1 = make_float2(c0.x - c2.x, c0.y - c2.y);
        float2 t2 = make_float2(c1.x + c3.x, c1.y + c3.y);
        float2 t3 = make_float2(c1.x - c3.x, c1.y - c3.y);
        float2 u3 = make_float2(-sgn * t3.y, sgn * t3.x);   // (-+i)*t3
        float2 e0 = make_float2(t0.x + t2.x, t0.y + t2.y);
        float2 d1 = make_float2(t0.x - t2.x, t0.y - t2.y);
        float2 d2 = make_float2(t1.x + u3.x, t1.y + u3.y);
        float2 d3 = make_float2(t1.x - u3.x, t1.y - u3.y);
        int B = o + 3 * k + t;                              // o + 4k + (t-k)
        b[SK(B)]         = e0;
        b[SK(B + m)]     = cmul_sgn(tw[k],     d2, sgn);
        b[SK(B + 2*m)]   = cmul_sgn(tw[2 * k], d1, sgn);
        b[SK(B + 3*m)]   = cmul_sgn(tw[3 * k], d3, sgn);
        barx(bid);
        float2* tp = a; a = b; b = tp;
    }
}

__device__ __forceinline__ void fill_tw(float2* tw, int tid, int nthreads) {
    for (int i = tid; i < 192; i += nthreads) {
        float s, c;
        sincospif((float)i / 128.0f, &s, &c);
        tw[i] = make_float2(c, s);
    }
}

// Stage A: x-blur + forward rfft of TWO rows packed per transform.
// 256-thread block = 4 transforms = 8 rows.
__global__ void fftA_kernel() {
    __shared__ float2 buf0[1056], buf1[1056], tw[192];
    float* raw = (float*)buf1;               // 2048 floats = 8 raw rows
    int tid = threadIdx.x;
    int c = tid >> 6, t = tid & 63;
    int b  = blockIdx.x >> 5;
    int y0 = (blockIdx.x & 31) * 8;
    const float* src = &g_img[(b * 256 + y0) * 256];
    #pragma unroll
    for (int j = 0; j < 8; j++) raw[tid + j * 256] = src[tid + j * 256];
    fill_tw(tw, tid, 256);
    float w[7];
    #pragma unroll
    for (int i = 0; i < 7; i++) w[i] = g_gauss[i];
    __syncthreads();                         // raw + tw visible to all

    // x-blur rows 2c, 2c+1 (zero-padded SAME)
    float2 zz[4];
    #pragma unroll
    for (int j = 0; j < 4; j++) {
        int x = t + 64 * j;
        float a0 = 0.f, a1 = 0.f;
        #pragma unroll
        for (int d = -3; d <= 3; d++) {
            int xx = x + d;
            if (xx >= 0 && xx < 256) {
                a0 = fmaf(w[d+3], raw[(2*c)   * 256 + xx], a0);
                a1 = fmaf(w[d+3], raw[(2*c+1) * 256 + xx], a1);
            }
        }
        zz[j] = make_float2(a0, a1);
    }
    __syncthreads();                         // all raw reads before buf1 writes
    #pragma unroll
    for (int j = 0; j < 4; j++) buf0[SK(c * 256 + t + 64 * j)] = zz[j];
    // no barrier: FFT stage 1 reads exactly this thread's written elements
    fft256_r4(buf0, buf1, tw, c * 256, t, -1.0f, 1 + c);

    // Unpack packed real FFT: A1 = (Z + conj(Zr))/2 ; A2 = -i(Z - conj(Zr))/2
    float2* o1 = &g_A[(size_t)(b * 256 + y0 + 2 * c) * AST];
    float2* o2 = o1 + AST;
    #pragma unroll
    for (int j = 0; j < 2; j++) {
        int kx = t + 64 * j;
        float2 Z1 = buf0[SK(c * 256 + kx)];
        float2 Z2 = buf0[SK(c * 256 + ((256 - kx) & 255))];
        o1[kx] = make_float2(0.5f*(Z1.x + Z2.x), 0.5f*(Z1.y - Z2.y));
        o2[kx] = make_float2(0.5f*(Z1.y + Z2.y), 0.5f*(Z2.x - Z1.x));
    }
    if (t == 0) {
        float2 Zn = buf0[SK(c * 256 + 128)];
        o1[128] = make_float2(Zn.x, 0.f);
        o2[128] = make_float2(Zn.y, 0.f);
    }
}

// Stage B: y-blur + column fwd FFT + CTF + column inv FFT.
// 256-thread block = 4 kx columns (64-thread transforms). raw aliases buf1.
__global__ void fftB_kernel(const float* __restrict__ ctf) {
    __shared__ float2 buf0[1056], buf1[1056], tw[192];
    float2* raw = buf1;
    int tid = threadIdx.x;
    int c = tid >> 6, t = tid & 63;
    int b   = blockIdx.x / 33;
    int kx0 = (blockIdx.x % 33) * 4;

    #pragma unroll
    for (int r = 0; r < 4; r++) {
        int e  = tid + r * 256;
        int cc = e & 3, ky = e >> 2;
        int kx = min(kx0 + cc, 128);
        raw[cc * 256 + ky] = g_A[(size_t)(b * 256 + ky) * AST + kx];
    }
    fill_tw(tw, tid, 256);
    float w[7];
    #pragma unroll
    for (int i = 0; i < 7; i++) w[i] = g_gauss[i];
    __syncthreads();                         // raw + tw visible

    // y-blur (zero-padded); row index here is spatial y
    float2 zz[4];
    #pragma unroll
    for (int j = 0; j < 4; j++) {
        int y = t + 64 * j;
        float2 acc = make_float2(0.f, 0.f);
        #pragma unroll
        for (int d = -3; d <= 3; d++) {
            int yy = y + d;
            if (yy >= 0 && yy < 256) {
                float2 v = raw[c * 256 + yy];
                acc.x = fmaf(w[d+3], v.x, acc.x);
                acc.y = fmaf(w[d+3], v.y, acc.y);
            }
        }
        zz[j] = acc;
    }
    __syncthreads();                         // all raw reads before buf1 writes
    #pragma unroll
    for (int j = 0; j < 4; j++) buf0[SK(c * 256 + t + 64 * j)] = zz[j];
    // no barrier: stage-1 reads == this thread's writes
    fft256_r4(buf0, buf1, tw, c * 256, t, -1.0f, 1 + c);

    int kxc = min(kx0 + c, 128);
    #pragma unroll
    for (int j = 0; j < 4; j++) {
        int ky = t + 64 * j;
        float f = ctf[(size_t)(b * 256 + ky) * HALFK + kxc];
        float2 v = buf0[SK(c * 256 + ky)];
        buf0[SK(c * 256 + ky)] = make_float2(v.x * f, v.y * f);
    }
    // no barrier: inverse stage-1 reads == this thread's CTF writes
    fft256_r4(buf0, buf1, tw, c * 256, t, 1.0f, 1 + c);

    __syncthreads();                         // cross-transform store below
    #pragma unroll
    for (int r = 0; r < 4; r++) {
        int e  = tid + r * 256;
        int cc = e & 3, ky = e >> 2;
        int kx = kx0 + cc;
        if (kx <= 128)
            g_A[(size_t)(b * 256 + ky) * AST + kx] = buf0[SK(cc * 256 + ky)];
    }
}

// Stage D: inverse rfft of TWO rows per transform (S1 + i*S2 pack).
// Im of DC/Nyquist dropped (irfft semantics; keeps pack exactly Hermitian).
__global__ void fftD_kernel(float* __restrict__ out) {
    __shared__ float2 buf0[1056], buf1[1056], tw[192];
    int tid = threadIdx.x;
    int c = tid >> 6, t = tid & 63;
    int b  = blockIdx.x >> 5;
    int y0 = (blockIdx.x & 31) * 8 + 2 * c;
    const float2* A1 = &g_A[(size_t)(b * 256 + y0) * AST];
    const float2* A2 = A1 + AST;
    int o = c * 256;

    if (t == 0) {
        buf0[SK(o + 0)]   = make_float2(A1[0].x,   A2[0].x);    // Im(DC) dropped
        buf0[SK(o + 128)] = make_float2(A1[128].x, A2[128].x);  // Im(Nyq) dropped
    } else {
        float2 a1 = A1[t], a2 = A2[t];
        buf0[SK(o + t)] = make_float2(a1.x - a2.y, a1.y + a2.x);
        int m = 128 - t;                                        // j = t+128
        float2 m1 = A1[m], m2 = A2[m];
        buf0[SK(o + t + 128)] = make_float2(m1.x + m2.y, m2.x - m1.y);
    }
    {
        int j = t + 64;                                         // [64,128)
        float2 a1 = A1[j], a2 = A2[j];
        buf0[SK(o + j)] = make_float2(a1.x - a2.y, a1.y + a2.x);
    }
    {
        int m = 64 - t;                                         // j = t+192
        float2 m1 = A1[m], m2 = A2[m];
        buf0[SK(o + t + 192)] = make_float2(m1.x + m2.y, m2.x - m1.y);
    }
    fill_tw(tw, tid, 256);
    __syncthreads();                         // tw visible (pack is own-thread)
    fft256_r4(buf0, buf1, tw, o, t, 1.0f, 1 + c);

    const float s = 1.0f / 65536.0f;   // 1/(256*256)
    float* o0 = &out[(size_t)(b * 256 + y0) * 256];
    float* o1 = o0 + 256;
    #pragma unroll
    for (int j = 0; j < 4; j++) {
        float2 v = buf0[SK(o + t + 64 * j)];
        o0[t + 64 * j] = v.x * s;
        o1[t + 64 * j] = v.y * s;
    }
}

// ---------------- launch ----------------
extern "C" void kernel_launch(void* const* d_in, const int* in_sizes, int n_in,
                              void* d_out, int out_size) {
    const float* rows   = (const float*)d_in[0];
    const float* shifts = (const float*)d_in[1];
    const float* latent = (const float*)d_in[2];
    const float* coords = (const float*)d_in[3];
    const float* values = (const float*)d_in[4];
    const float* W0 = (const float*)d_in[5];
    const float* b0 = (const float*)d_in[6];
    const float* W1 = (const float*)d_in[7];
    const float* b1 = (const float*)d_in[8];
    const float* W2 = (const float*)d_in[9];
    const float* b2 = (const float*)d_in[10];
    const float* W3 = (const float*)d_in[11];
    const float* b3 = (const float*)d_in[12];
    const float* Wd = (const float*)d_in[13];
    const float* bd = (const float*)d_in[14];
    const float* ctf = (const float*)d_in[15];
    int N = in_sizes[4];

    zero_prep_kernel<<<NPIX / 4 / 256, 256>>>(rows, shifts, latent,
                                              W0, b0, W1, b1, W2, b2, W3, b3);
    scatter_kernel<<<(N + 255) / 256, 256>>>(coords, values, Wd, bd, N);
    fftA_kernel<<<BB * 32, 256>>>();
    fftB_kernel<<<BB * 33, 256>>>(ctf);
    fftD_kernel<<<BB * 32, 256>>>((float*)d_out);
}

// round 16
// speedup vs baseline: 1.4424x; 1.0106x over previous
#include <cuda_runtime.h>
#include <math.h>

#define XS   256
#define BB   16
#define HALFK 129               // XS/2 + 1 (logical)
#define AST   132               // allocated g_A row stride (1056B, 32B-aligned)
#define NPIX (BB * XS * XS)
#define SK(i) ((i) + ((i) >> 5))   // smem bank skew

// ---------------- scratch (device globals: no allocation allowed) ----------
__device__ float  g_prep[BB * 16];      // per batch: R00..R12 (6), s0, s1, h[8]
__device__ float  g_gauss[7];
__device__ float  g_img[NPIX];          // scatter target
__device__ __align__(128) float2 g_A[BB * XS * AST]; // half-spectrum [b][y/ky][kx]

// 64-thread named barrier (2 warps of one transform). ids 1..4.
__device__ __forceinline__ void barx(int id) {
    asm volatile("bar.sync %0, 64;" :: "r"(id) : "memory");
}

// ---------------- fused zero + prep + gaussian taps ----------------
__global__ void zero_prep_kernel(const float* __restrict__ rows,
                                 const float* __restrict__ shifts,
                                 const float* __restrict__ latent,
                                 const float* __restrict__ W0, const float* __restrict__ b0,
                                 const float* __restrict__ W1, const float* __restrict__ b1,
                                 const float* __restrict__ W2, const float* __restrict__ b2,
                                 const float* __restrict__ W3, const float* __restrict__ b3) {
    if (blockIdx.x == 0) {
        int b = threadIdx.x;
        if (b < BB) {
            float rot = rows[b*3+0], tilt = rows[b*3+1], psi = rows[b*3+2];
            float ca = cosf(rot),  sa = sinf(rot);
            float cb = cosf(tilt), sb = sinf(tilt);
            float cg = cosf(psi),  sg = sinf(psi);
            float nsg = -sg;
            float* p = &g_prep[b * 16];
            p[0] = __fsub_rn(__fmul_rn(__fmul_rn(cg, cb), ca), __fmul_rn(sg, sa));
            p[1] = __fadd_rn(__fmul_rn(__fmul_rn(cg, cb), sa), __fmul_rn(sg, ca));
            p[2] = -__fmul_rn(cg, sb);
            p[3] = __fsub_rn(__fmul_rn(__fmul_rn(nsg, cb), ca), __fmul_rn(cg, sa));
            p[4] = __fadd_rn(__fmul_rn(__fmul_rn(nsg, cb), sa), __fmul_rn(cg, ca));
            p[5] = __fmul_rn(sg, sb);
            p[6] = shifts[b*2+0];
            p[7] = shifts[b*2+1];

            float h[8];
            #pragma unroll
            for (int j = 0; j < 8; j++) {
                float acc = b0[j];
                #pragma unroll
                for (int l = 0; l < 8; l++) acc += latent[b*8+l] * W0[l*8+j];
                h[j] = sinf(30.0f * acc);
            }
            const float* Ws[3] = {W1, W2, W3};
            const float* bs[3] = {b1, b2, b3};
            for (int s = 0; s < 3; s++) {
                float t[8];
                #pragma unroll
                for (int j = 0; j < 8; j++) {
                    float acc = bs[s][j];
                    #pragma unroll
                    for (int l = 0; l < 8; l++) acc += h[l] * Ws[s][l*8+j];
                    t[j] = sinf(acc);
                }
                #pragma unroll
                for (int j = 0; j < 8; j++) h[j] += t[j];
            }
            #pragma unroll
            for (int j = 0; j < 8; j++) p[8+j] = h[j];
        }
        if (threadIdx.x == 0) {
            float k[7], s = 0.f;
            for (int i = 0; i < 7; i++) { float x = (float)(i - 3); k[i] = expf(-0.5f * x * x); s += k[i]; }
            for (int i = 0; i < 7; i++) g_gauss[i] = k[i] / s;
        }
    }
    int i = blockIdx.x * blockDim.x + threadIdx.x;
    float4* p4 = (float4*)g_img;
    if (i < NPIX / 4) p4[i] = make_float4(0.f, 0.f, 0.f, 0.f);
}

// ---------------- scatter (arithmetic bit-identical to passing rounds) ------
__global__ void scatter_kernel(const float* __restrict__ coords,
                               const float* __restrict__ values,
                               const float* __restrict__ Wd,
                               const float* __restrict__ bd,
                               int N) {
    __shared__ float sp[256];  // 16 batches x 16 floats
    if (threadIdx.x < 256) sp[threadIdx.x] = g_prep[threadIdx.x];
    __syncthreads();

    int n = blockIdx.x * blockDim.x + threadIdx.x;
    if (n >= N) return;

    float cx = coords[n*3+0], cy = coords[n*3+1], cz = coords[n*3+2];
    float base = values[n] + bd[n];
    float wd[8];
    #pragma unroll
    for (int l = 0; l < 8; l++) wd[l] = Wd[(size_t)l * N + n];

    #pragma unroll
    for (int b = 0; b < BB; b++) {
        const float* p = &sp[b * 16];
        float xr = __fmaf_rn(p[2], cz, __fmaf_rn(p[1], cy, __fmul_rn(p[0], cx)));
        float yr = __fmaf_rn(p[5], cz, __fmaf_rn(p[4], cy, __fmul_rn(p[3], cx)));
        float fx = rintf(__fadd_rn(__fadd_rn(xr, p[6]), 128.0f));
        float fy = rintf(__fadd_rn(__fadd_rn(yr, p[7]), 128.0f));
        fx = fminf(fmaxf(fx, 0.f), 255.f);
        fy = fminf(fmaxf(fy, 0.f), 255.f);
        int ix = (int)fx, iy = (int)fy;
        float val = base;
        #pragma unroll
        for (int l = 0; l < 8; l++) val = fmaf(p[8+l], wd[l], val);
        atomicAdd(&g_img[(b << 16) + (iy << 8) + ix], val);
    }
}

// ---------------- radix-4 Stockham 256-pt FFT (64 threads / transform) -----
// tw[k] = e^{+2pi i k/256}. sgn=-1 fwd, +1 inv (unnormalized). Result in b0.
__device__ __forceinline__ float2 cmul_sgn(float2 w, float2 v, float sgn) {
    float wy = sgn * w.y;
    return make_float2(fmaf(w.x, v.x, -wy * v.y), fmaf(w.x, v.y, wy * v.x));
}

__device__ __forceinline__ void fft256_r4(float2* b0, float2* b1, const float2* tw,
                                          int o, int t, float sgn, int bid) {
    float2 *a = b0, *b = b1;
    #pragma unroll
    for (int m = 1; m < 256; m <<= 2) {
        int k = t & ~(m - 1);
        float2 c0 = a[SK(o + t)],       c1 = a[SK(o + t + 64)];
        float2 c2 = a[SK(o + t + 128)], c3 = a[SK(o + t + 192)];
        float2 t0 = make_float2(c0.x + c2.x, c0.y + c2.y);
        float2 t1 = make_float2(c0.x - c2.x, c0.y - c2.y);
        float2 t2 = make_float2(c1.x + c3.x, c1.y + c3.y);
        float2 t3 = make_float2(c1.x - c3.x, c1.y - c3.y);
        float2 u3 = make_float2(-sgn * t3.y, sgn * t3.x);   // (-+i)*t3
        float2 e0 = make_float2(t0.x + t2.x, t0.y + t2.y);
        float2 d1 = make_float2(t0.x - t2.x, t0.y - t2.y);
        float2 d2 = make_float2(t1.x + u3.x, t1.y + u3.y);
        float2 d3 = make_float2(t1.x - u3.x, t1.y - u3.y);
        int B = o + 3 * k + t;                              // o + 4k + (t-k)
        b[SK(B)]         = e0;
        b[SK(B + m)]     = cmul_sgn(tw[k],     d2, sgn);
        b[SK(B + 2*m)]   = cmul_sgn(tw[2 * k], d1, sgn);
        b[SK(B + 3*m)]   = cmul_sgn(tw[3 * k], d3, sgn);
        barx(bid);
        float2* tp = a; a = b; b = tp;
    }
}

__device__ __forceinline__ void fill_tw(float2* tw, int tid, int nthreads) {
    for (int i = tid; i < 192; i += nthreads) {
        float s, c;
        sincospif((float)i / 128.0f, &s, &c);
        tw[i] = make_float2(c, s);
    }
}

// Stage A: x-blur + forward rfft of TWO rows packed per transform.
// 256-thread block = 4 transforms = 8 rows.
__global__ __launch_bounds__(256, 6) void fftA_kernel() {
    __shared__ float2 buf0[1056], buf1[1056], tw[192];
    float* raw = (float*)buf1;               // 2048 floats = 8 raw rows
    int tid = threadIdx.x;
    int c = tid >> 6, t = tid & 63;
    int b  = blockIdx.x >> 5;
    int y0 = (blockIdx.x & 31) * 8;
    const float* src = &g_img[(b * 256 + y0) * 256];
    #pragma unroll
    for (int j = 0; j < 8; j++) raw[tid + j * 256] = src[tid + j * 256];
    fill_tw(tw, tid, 256);
    float w[7];
    #pragma unroll
    for (int i = 0; i < 7; i++) w[i] = g_gauss[i];
    __syncthreads();                         // raw + tw visible to all

    // x-blur rows 2c, 2c+1 (zero-padded SAME)
    float2 zz[4];
    #pragma unroll
    for (int j = 0; j < 4; j++) {
        int x = t + 64 * j;
        float a0 = 0.f, a1 = 0.f;
        #pragma unroll
        for (int d = -3; d <= 3; d++) {
            int xx = x + d;
            if (xx >= 0 && xx < 256) {
                a0 = fmaf(w[d+3], raw[(2*c)   * 256 + xx], a0);
                a1 = fmaf(w[d+3], raw[(2*c+1) * 256 + xx], a1);
            }
        }
        zz[j] = make_float2(a0, a1);
    }
    __syncthreads();                         // all raw reads before buf1 writes
    #pragma unroll
    for (int j = 0; j < 4; j++) buf0[SK(c * 256 + t + 64 * j)] = zz[j];
    // no barrier: FFT stage 1 reads exactly this thread's written elements
    fft256_r4(buf0, buf1, tw, c * 256, t, -1.0f, 1 + c);

    // Unpack packed real FFT: A1 = (Z + conj(Zr))/2 ; A2 = -i(Z - conj(Zr))/2
    float2* o1 = &g_A[(size_t)(b * 256 + y0 + 2 * c) * AST];
    float2* o2 = o1 + AST;
    #pragma unroll
    for (int j = 0; j < 2; j++) {
        int kx = t + 64 * j;
        float2 Z1 = buf0[SK(c * 256 + kx)];
        float2 Z2 = buf0[SK(c * 256 + ((256 - kx) & 255))];
        o1[kx] = make_float2(0.5f*(Z1.x + Z2.x), 0.5f*(Z1.y - Z2.y));
        o2[kx] = make_float2(0.5f*(Z1.y + Z2.y), 0.5f*(Z2.x - Z1.x));
    }
    if (t == 0) {
        float2 Zn = buf0[SK(c * 256 + 128)];
        o1[128] = make_float2(Zn.x, 0.f);
        o2[128] = make_float2(Zn.y, 0.f);
    }
}

// Stage B: y-blur + column fwd FFT + CTF + column inv FFT.
// 256-thread block = 4 kx columns (64-thread transforms). raw aliases buf1.
__global__ __launch_bounds__(256, 6) void fftB_kernel(const float* __restrict__ ctf) {
    __shared__ float2 buf0[1056], buf1[1056], tw[192];
    float2* raw = buf1;
    int tid = threadIdx.x;
    int c = tid >> 6, t = tid & 63;
    int b   = blockIdx.x / 33;
    int kx0 = (blockIdx.x % 33) * 4;

    #pragma unroll
    for (int r = 0; r < 4; r++) {
        int e  = tid + r * 256;
        int cc = e & 3, ky = e >> 2;
        int kx = min(kx0 + cc, 128);
        raw[cc * 256 + ky] = g_A[(size_t)(b * 256 + ky) * AST + kx];
    }
    fill_tw(tw, tid, 256);
    float w[7];
    #pragma unroll
    for (int i = 0; i < 7; i++) w[i] = g_gauss[i];
    __syncthreads();                         // raw + tw visible

    // y-blur (zero-padded); row index here is spatial y
    float2 zz[4];
    #pragma unroll
    for (int j = 0; j < 4; j++) {
        int y = t + 64 * j;
        float2 acc = make_float2(0.f, 0.f);
        #pragma unroll
        for (int d = -3; d <= 3; d++) {
            int yy = y + d;
            if (yy >= 0 && yy < 256) {
                float2 v = raw[c * 256 + yy];
                acc.x = fmaf(w[d+3], v.x, acc.x);
                acc.y = fmaf(w[d+3], v.y, acc.y);
            }
        }
        zz[j] = acc;
    }
    __syncthreads();                         // all raw reads before buf1 writes
    #pragma unroll
    for (int j = 0; j < 4; j++) buf0[SK(c * 256 + t + 64 * j)] = zz[j];
    // no barrier: stage-1 reads == this thread's writes
    fft256_r4(buf0, buf1, tw, c * 256, t, -1.0f, 1 + c);

    int kxc = min(kx0 + c, 128);
    #pragma unroll
    for (int j = 0; j < 4; j++) {
        int ky = t + 64 * j;
        float f = ctf[(size_t)(b * 256 + ky) * HALFK + kxc];
        float2 v = buf0[SK(c * 256 + ky)];
        buf0[SK(c * 256 + ky)] = make_float2(v.x * f, v.y * f);
    }
    // no barrier: inverse stage-1 reads == this thread's CTF writes
    fft256_r4(buf0, buf1, tw, c * 256, t, 1.0f, 1 + c);

    __syncthreads();                         // cross-transform store below
    #pragma unroll
    for (int r = 0; r < 4; r++) {
        int e  = tid + r * 256;
        int cc = e & 3, ky = e >> 2;
        int kx = kx0 + cc;
        if (kx <= 128)
            g_A[(size_t)(b * 256 + ky) * AST + kx] = buf0[SK(cc * 256 + ky)];
    }
}

// Stage D: inverse rfft of TWO rows per transform (S1 + i*S2 pack).
// Im of DC/Nyquist dropped (irfft semantics; keeps pack exactly Hermitian).
__global__ __launch_bounds__(256, 6) void fftD_kernel(float* __restrict__ out) {
    __shared__ float2 buf0[1056], buf1[1056], tw[192];
    int tid = threadIdx.x;
    int c = tid >> 6, t = tid & 63;
    int b  = blockIdx.x >> 5;
    int y0 = (blockIdx.x & 31) * 8 + 2 * c;
    const float2* A1 = &g_A[(size_t)(b * 256 + y0) * AST];
    const float2* A2 = A1 + AST;
    int o = c * 256;

    if (t == 0) {
        buf0[SK(o + 0)]   = make_float2(A1[0].x,   A2[0].x);    // Im(DC) dropped
        buf0[SK(o + 128)] = make_float2(A1[128].x, A2[128].x);  // Im(Nyq) dropped
    } else {
        float2 a1 = A1[t], a2 = A2[t];
        buf0[SK(o + t)] = make_float2(a1.x - a2.y, a1.y + a2.x);
        int m = 128 - t;                                        // j = t+128
        float2 m1 = A1[m], m2 = A2[m];
        buf0[SK(o + t + 128)] = make_float2(m1.x + m2.y, m2.x - m1.y);
    }
    {
        int j = t + 64;                                         // [64,128)
        float2 a1 = A1[j], a2 = A2[j];
        buf0[SK(o + j)] = make_float2(a1.x - a2.y, a1.y + a2.x);
    }
    {
        int m = 64 - t;                                         // j = t+192
        float2 m1 = A1[m], m2 = A2[m];
        buf0[SK(o + t + 192)] = make_float2(m1.x + m2.y, m2.x - m1.y);
    }
    fill_tw(tw, tid, 256);
    __syncthreads();                         // tw visible (pack is own-thread)
    fft256_r4(buf0, buf1, tw, o, t, 1.0f, 1 + c);

    const float s = 1.0f / 65536.0f;   // 1/(256*256)
    float* o0 = &out[(size_t)(b * 256 + y0) * 256];
    float* o1 = o0 + 256;
    #pragma unroll
    for (int j = 0; j < 4; j++) {
        float2 v = buf0[SK(o + t + 64 * j)];
        o0[t + 64 * j] = v.x * s;
        o1[t + 64 * j] = v.y * s;
    }
}

// ---------------- launch ----------------
extern "C" void kernel_launch(void* const* d_in, const int* in_sizes, int n_in,
                              void* d_out, int out_size) {
    const float* rows   = (const float*)d_in[0];
    const float* shifts = (const float*)d_in[1];
    const float* latent = (const float*)d_in[2];
    const float* coords = (const float*)d_in[3];
    const float* values = (const float*)d_in[4];
    const float* W0 = (const float*)d_in[5];
    const float* b0 = (const float*)d_in[6];
    const float* W1 = (const float*)d_in[7];
    const float* b1 = (const float*)d_in[8];
    const float* W2 = (const float*)d_in[9];
    const float* b2 = (const float*)d_in[10];
    const float* W3 = (const float*)d_in[11];
    const float* b3 = (const float*)d_in[12];
    const float* Wd = (const float*)d_in[13];
    const float* bd = (const float*)d_in[14];
    const float* ctf = (const float*)d_in[15];
    int N = in_sizes[4];

    zero_prep_kernel<<<NPIX / 4 / 256, 256>>>(rows, shifts, latent,
                                              W0, b0, W1, b1, W2, b2, W3, b3);
    scatter_kernel<<<(N + 255) / 256, 256>>>(coords, values, Wd, bd, N);
    fftA_kernel<<<BB * 32, 256>>>();
    fftB_kernel<<<BB * 33, 256>>>(ctf);
    fftD_kernel<<<BB * 32, 256>>>((float*)d_out);
}